// round 4
// baseline (speedup 1.0000x reference)
#include <cuda_runtime.h>
#include <cstdint>

// Problem constants (fixed by reference)
#define BWIN   2048
#define NTOK   49
#define CDIM   384
#define HHEADS 12
#define DH     32
#define NWMASK 64
#define THREEC 1152
#define MROWS  (BWIN * NTOK)   // 100352

// Scratch (allocation-free rule: __device__ globals)
__device__ float g_qkv[(size_t)MROWS * THREEC];   // [M, 1152]
__device__ float g_att[(size_t)MROWS * CDIM];     // [M, 384]  (tf32-rounded)
__device__ float g_x  [(size_t)MROWS * CDIM];     // x, tf32-rounded
__device__ float g_wq [(size_t)THREEC * CDIM];    // qkv_w, tf32-rounded
__device__ float g_wp [(size_t)CDIM * CDIM];      // proj_w, tf32-rounded

// ---------------------------------------------------------------------------
// helpers
// ---------------------------------------------------------------------------
__device__ __forceinline__ uint32_t f2tf32(float f) {
    uint32_t u;
    asm("cvt.rna.tf32.f32 %0, %1;" : "=r"(u) : "f"(f));
    return u;
}

__device__ __forceinline__ void mma_tf32(float c[4],
                                         uint32_t a0, uint32_t a1, uint32_t a2, uint32_t a3,
                                         uint32_t b0, uint32_t b1) {
    asm volatile(
        "mma.sync.aligned.m16n8k8.row.col.f32.tf32.tf32.f32 "
        "{%0,%1,%2,%3}, {%4,%5,%6,%7}, {%8,%9}, {%0,%1,%2,%3};"
        : "+f"(c[0]), "+f"(c[1]), "+f"(c[2]), "+f"(c[3])
        : "r"(a0), "r"(a1), "r"(a2), "r"(a3), "r"(b0), "r"(b1));
}

#define CPA16(dst, src) \
    asm volatile("cp.async.cg.shared.global [%0], [%1], 16;\n" :: "r"(dst), "l"(src))
#define CP_COMMIT() asm volatile("cp.async.commit_group;\n" ::)
template <int N>
__device__ __forceinline__ void cp_wait() {
    asm volatile("cp.async.wait_group %0;\n" :: "n"(N));
}

// ---------------------------------------------------------------------------
// prepass: round fp32 -> tf32 (rna), stored as fp32 bit pattern
// ---------------------------------------------------------------------------
__global__ void round_tf32_kernel(const float* __restrict__ in,
                                  float* __restrict__ out, int n4)
{
    const int i = blockIdx.x * blockDim.x + threadIdx.x;
    if (i < n4) {
        const float4 v = ((const float4*)in)[i];
        uint4 u;
        u.x = f2tf32(v.x); u.y = f2tf32(v.y);
        u.z = f2tf32(v.z); u.w = f2tf32(v.w);
        ((uint4*)out)[i] = u;
    }
}

// ---------------------------------------------------------------------------
// tf32 tensor-core GEMM v3 (cp.async 3-stage):  C = A @ W^T + bias
// CTA tile 256x128, BK=16, 256 threads = 8 warps (4m x 2n), warp tile 64x64.
// Fragment-permuted smem (16B unit = 4 consecutive k of one row -> cp.async OK):
//   A word idx: ((k8*16 + mi)*4 + kh*2 + hi)*32 + g2*4 + kk
//   B word idx: ((k8*16 + ni)*2 + kh)*32 + g2*4 + kk
// Inputs MUST already be tf32-rounded (prepass) — truncation here is identity.
// ---------------------------------------------------------------------------
#define STAGES 3
#define AW 4096   // A words/stage (256*16)
#define BW 2048   // B words/stage (128*16)

__global__ __launch_bounds__(256, 1) void gemm_tf32_v3(
    const float* __restrict__ A,
    const float* __restrict__ W,
    const float* __restrict__ bias,
    float* __restrict__ C,
    int Nout, int K)
{
    __shared__ __align__(16) uint32_t As[STAGES * AW];
    __shared__ __align__(16) uint32_t Bs[STAGES * BW];

    const int tid  = threadIdx.x;
    const int bm   = blockIdx.y * 256;
    const int bn   = blockIdx.x * 128;
    const int lane = tid & 31;
    const int warp = tid >> 5;
    const int warp_m = warp >> 1;    // 0..3  (64-row slab)
    const int warp_n = warp & 1;     // 0..1  (64-col slab)
    const int g = lane >> 2;
    const int t = lane & 3;

    // loader mapping: A 256x16 -> 4 chunks/thread, B 128x16 -> 2 chunks/thread
    const int ldr = tid >> 2;            // 0..63
    const int ldc = (tid & 3) << 2;      // 0,4,8,12
    const int k8s = ldc >> 3;            // 0,0,1,1
    const int khs = (ldc >> 2) & 1;      // 0,1,0,1

    const float* Ab = A + (size_t)(bm + ldr) * K + ldc;
    const float* Wb = W + (size_t)(bn + ldr) * K + ldc;

    // smem dst byte-offsets per chunk
    uint32_t aoff[4], boff[2];
#pragma unroll
    for (int i = 0; i < 4; ++i) {
        const int r  = ldr + i * 64;
        const int mi = r >> 4;
        const int g2 = r & 7;
        const int hi = (r >> 3) & 1;
        aoff[i] = (((k8s * 16 + mi) * 4 + (khs * 2 + hi)) * 32 + g2 * 4) * 4u;
    }
#pragma unroll
    for (int i = 0; i < 2; ++i) {
        const int cL = ldr + i * 64;
        const int ni = cL >> 3;
        const int g2 = cL & 7;
        boff[i] = (((k8s * 16 + ni) * 2 + khs) * 32 + g2 * 4) * 4u;
    }

    const uint32_t As0 = (uint32_t)__cvta_generic_to_shared(As);
    const uint32_t Bs0 = (uint32_t)__cvta_generic_to_shared(Bs);

    const int NS = K / 16;   // 24

    auto issue = [&](int s) {
        const int buf = s % STAGES;
        const int k0  = s * 16;
        const uint32_t ab = As0 + buf * (AW * 4);
        const uint32_t bb = Bs0 + buf * (BW * 4);
        CPA16(ab + aoff[0], Ab + k0);
        CPA16(ab + aoff[1], Ab + (size_t)64  * K + k0);
        CPA16(ab + aoff[2], Ab + (size_t)128 * K + k0);
        CPA16(ab + aoff[3], Ab + (size_t)192 * K + k0);
        CPA16(bb + boff[0], Wb + k0);
        CPA16(bb + boff[1], Wb + (size_t)64  * K + k0);
        CP_COMMIT();
    };

    // prologue: stages 0..STAGES-2 in flight
    issue(0);
    issue(1);
    cp_wait<STAGES - 2>();   // stage 0 landed
    __syncthreads();

    float acc[4][8][4] = {};

    for (int s = 0; s < NS; ++s) {
        // refill the buffer consumed at iter s-1 (ordered by last syncthreads)
        if (s + STAGES - 1 < NS) issue(s + STAGES - 1);
        else CP_COMMIT();   // keep group accounting uniform

        const int buf = s % STAGES;
        const uint32_t* Abase = As + buf * AW;
        const uint32_t* Bbase = Bs + buf * BW;

#pragma unroll
        for (int k8 = 0; k8 < 2; ++k8) {
            uint32_t af[4][4], bfr[8][2];
            const uint32_t* Ap = Abase + ((k8 * 16 + warp_m * 4) * 4) * 32 + lane;
            const uint32_t* Bp = Bbase + ((k8 * 16 + warp_n * 8) * 2) * 32 + lane;
#pragma unroll
            for (int mi = 0; mi < 4; ++mi)
#pragma unroll
                for (int r = 0; r < 4; ++r)
                    af[mi][r] = Ap[(mi * 4 + r) * 32];
#pragma unroll
            for (int ni = 0; ni < 8; ++ni) {
                bfr[ni][0] = Bp[ni * 64];
                bfr[ni][1] = Bp[ni * 64 + 32];
            }
#pragma unroll
            for (int mi = 0; mi < 4; ++mi)
#pragma unroll
                for (int ni = 0; ni < 8; ++ni)
                    mma_tf32(acc[mi][ni],
                             af[mi][0], af[mi][1], af[mi][2], af[mi][3],
                             bfr[ni][0], bfr[ni][1]);
        }

        cp_wait<STAGES - 2>();   // next stage landed
        __syncthreads();
    }

    // epilogue: frag layout m16n8: c0=(g,2t) c1=(g,2t+1) c2=(g+8,2t) c3=(g+8,2t+1)
#pragma unroll
    for (int mi = 0; mi < 4; ++mi) {
#pragma unroll
        for (int ni = 0; ni < 8; ++ni) {
            const int row = bm + warp_m * 64 + mi * 16 + g;
            const int col = bn + warp_n * 64 + ni * 8 + 2 * t;
            const float b0v = __ldg(bias + col);
            const float b1v = __ldg(bias + col + 1);
            float2 v0 = make_float2(acc[mi][ni][0] + b0v, acc[mi][ni][1] + b1v);
            float2 v1 = make_float2(acc[mi][ni][2] + b0v, acc[mi][ni][3] + b1v);
            *(float2*)(C + (size_t)row * Nout + col)       = v0;
            *(float2*)(C + (size_t)(row + 8) * Nout + col) = v1;
        }
    }
}

// ---------------------------------------------------------------------------
// Attention: one CTA (128 threads) per (window b, head h).
// Output stored tf32-rounded so proj GEMM's cp.async path needs no conversion.
// ---------------------------------------------------------------------------
__global__ __launch_bounds__(128) void attn_kernel(const float* __restrict__ mask)
{
    const int b = blockIdx.x;   // 0..2047
    const int h = blockIdx.y;   // 0..11
    const int tid = threadIdx.x;

    __shared__ __align__(16) float qs[NTOK][DH];
    __shared__ __align__(16) float ks[NTOK][36];
    __shared__ __align__(16) float vs[NTOK][DH];
    __shared__ float sc[NTOK][53];

    const float scale = 0.17677669529663687f;  // 32^-0.5

    for (int idx = tid; idx < NTOK * DH; idx += 128) {
        const int n = idx >> 5;
        const int d = idx & 31;
        const float* base = g_qkv + (size_t)(b * NTOK + n) * THREEC + h * DH + d;
        qs[n][d] = base[0] * scale;
        ks[n][d] = base[CDIM];
        vs[n][d] = base[2 * CDIM];
    }
    __syncthreads();

    // scores: thread (half, j) owns key column j in registers
    {
        const int half = tid >> 6;
        const int j = tid & 63;
        if (j < NTOK) {
            float4 kv[8];
#pragma unroll
            for (int dd = 0; dd < 8; ++dd) kv[dd] = *(const float4*)&ks[j][dd * 4];
            const float* mcol = mask + (size_t)(b & (NWMASK - 1)) * NTOK * NTOK + j;
            const int i0 = half ? 25 : 0;
            const int i1 = half ? NTOK : 25;
            for (int i = i0; i < i1; ++i) {
                const float4* q4 = (const float4*)qs[i];
                float s = 0.0f;
#pragma unroll
                for (int dd = 0; dd < 8; ++dd) {
                    const float4 q = q4[dd];
                    s += q.x * kv[dd].x + q.y * kv[dd].y + q.z * kv[dd].z + q.w * kv[dd].w;
                }
                sc[i][j] = s + mcol[i * NTOK];
            }
        }
    }
    __syncthreads();

    // row softmax
    if (tid < NTOK) {
        float m = -1e30f;
#pragma unroll 7
        for (int j = 0; j < NTOK; j++) m = fmaxf(m, sc[tid][j]);
        float sum = 0.0f;
#pragma unroll 7
        for (int j = 0; j < NTOK; j++) {
            const float e = __expf(sc[tid][j] - m);
            sc[tid][j] = e;
            sum += e;
        }
        const float inv = 1.0f / sum;
#pragma unroll 7
        for (int j = 0; j < NTOK; j++) sc[tid][j] *= inv;
    }
    __syncthreads();

    // P @ V: lane d, warp handles 4-row blocks; store tf32-rounded
    const int d = tid & 31;
    const int w = tid >> 5;
    for (int i0 = w * 4; i0 < NTOK; i0 += 16) {
        const int nrows = (NTOK - i0 < 4) ? (NTOK - i0) : 4;
        float o0 = 0.f, o1 = 0.f, o2 = 0.f, o3 = 0.f;
        for (int j = 0; j < NTOK; ++j) {
            const float vj = vs[j][d];
            o0 += sc[i0][j] * vj;
            if (nrows > 1) o1 += sc[i0 + 1][j] * vj;
            if (nrows > 2) o2 += sc[i0 + 2][j] * vj;
            if (nrows > 3) o3 += sc[i0 + 3][j] * vj;
        }
        float* op = g_att + (size_t)(b * NTOK + i0) * CDIM + h * DH + d;
        op[0] = __uint_as_float(f2tf32(o0));
        if (nrows > 1) op[CDIM]     = __uint_as_float(f2tf32(o1));
        if (nrows > 2) op[2 * CDIM] = __uint_as_float(f2tf32(o2));
        if (nrows > 3) op[3 * CDIM] = __uint_as_float(f2tf32(o3));
    }
}

// ---------------------------------------------------------------------------
// launch
// ---------------------------------------------------------------------------
extern "C" void kernel_launch(void* const* d_in, const int* in_sizes, int n_in,
                              void* d_out, int out_size)
{
    const float* x      = (const float*)d_in[0];
    const float* mask   = (const float*)d_in[1];
    const float* qkv_w  = (const float*)d_in[2];
    const float* qkv_b  = (const float*)d_in[3];
    const float* proj_w = (const float*)d_in[4];
    const float* proj_b = (const float*)d_in[5];
    float* out = (float*)d_out;

    float *qkv_ptr, *att_ptr, *x_ptr, *wq_ptr, *wp_ptr;
    cudaGetSymbolAddress((void**)&qkv_ptr, g_qkv);
    cudaGetSymbolAddress((void**)&att_ptr, g_att);
    cudaGetSymbolAddress((void**)&x_ptr,   g_x);
    cudaGetSymbolAddress((void**)&wq_ptr,  g_wq);
    cudaGetSymbolAddress((void**)&wp_ptr,  g_wp);

    // 0) tf32-round inputs (rna) so cp.async GEMMs are conversion-free
    {
        const int nx = (MROWS * CDIM) / 4;
        round_tf32_kernel<<<(nx + 255) / 256, 256>>>(x, x_ptr, nx);
        const int nq = (THREEC * CDIM) / 4;
        round_tf32_kernel<<<(nq + 255) / 256, 256>>>(qkv_w, wq_ptr, nq);
        const int np = (CDIM * CDIM) / 4;
        round_tf32_kernel<<<(np + 255) / 256, 256>>>(proj_w, wp_ptr, np);
    }
    // 1) QKV GEMM: [100352,384] @ [384,1152]^T (+b)
    {
        dim3 grid(THREEC / 128, MROWS / 256);
        gemm_tf32_v3<<<grid, 256>>>(x_ptr, wq_ptr, qkv_b, qkv_ptr, THREEC, CDIM);
    }
    // 2) windowed attention (writes tf32-rounded g_att)
    {
        dim3 grid(BWIN, HHEADS);
        attn_kernel<<<grid, 128>>>(mask);
    }
    // 3) Proj GEMM: [100352,384] @ [384,384]^T (+b)
    {
        dim3 grid(CDIM / 128, MROWS / 256);
        gemm_tf32_v3<<<grid, 256>>>(att_ptr, wp_ptr, proj_b, out, CDIM, CDIM);
    }
}

// round 6
// speedup vs baseline: 1.5479x; 1.5479x over previous
#include <cuda_runtime.h>
#include <cuda_fp16.h>
#include <cstdint>

// Problem constants (fixed by reference)
#define BWIN   2048
#define NTOK   49
#define CDIM   384
#define HHEADS 12
#define DH     32
#define NWMASK 64
#define THREEC 1152
#define MROWS  (BWIN * NTOK)   // 100352

// Scratch (allocation-free rule: __device__ globals)
__device__ float  g_qkv [(size_t)MROWS * THREEC];   // [M, 1152] fp32
__device__ __half g_xh  [(size_t)MROWS * CDIM];     // x, fp16
__device__ __half g_atth[(size_t)MROWS * CDIM];     // attention out, fp16
__device__ __half g_wqh [(size_t)THREEC * CDIM];    // qkv_w, fp16
__device__ __half g_wph [(size_t)CDIM * CDIM];      // proj_w, fp16

// ---------------------------------------------------------------------------
// helpers
// ---------------------------------------------------------------------------
__device__ __forceinline__ void mma_f16(float c[4],
                                        uint32_t a0, uint32_t a1, uint32_t a2, uint32_t a3,
                                        uint32_t b0, uint32_t b1) {
    asm volatile(
        "mma.sync.aligned.m16n8k16.row.col.f32.f16.f16.f32 "
        "{%0,%1,%2,%3}, {%4,%5,%6,%7}, {%8,%9}, {%0,%1,%2,%3};"
        : "+f"(c[0]), "+f"(c[1]), "+f"(c[2]), "+f"(c[3])
        : "r"(a0), "r"(a1), "r"(a2), "r"(a3), "r"(b0), "r"(b1));
}

// ---------------------------------------------------------------------------
// prepass: fp32 -> fp16 (rn); 8 floats per thread
// ---------------------------------------------------------------------------
__global__ void to_half_kernel(const float* __restrict__ in,
                               __half* __restrict__ out, int n8)
{
    const int i = blockIdx.x * blockDim.x + threadIdx.x;
    if (i < n8) {
        const float4 v0 = ((const float4*)in)[2 * i];
        const float4 v1 = ((const float4*)in)[2 * i + 1];
        __half2 h[4];
        h[0] = __floats2half2_rn(v0.x, v0.y);
        h[1] = __floats2half2_rn(v0.z, v0.w);
        h[2] = __floats2half2_rn(v1.x, v1.y);
        h[3] = __floats2half2_rn(v1.z, v1.w);
        ((uint4*)out)[i] = *(uint4*)h;
    }
}

// ---------------------------------------------------------------------------
// fp16 tensor-core GEMM:  C[m,n] = sum_k A[m,k]*W[n,k] + bias[n]   (fp32 accum)
// A: [M,K] fp16 row-major, W: [Nout,K] fp16 row-major.
// CTA tile 256x128, BK=32 halfs (2 x k16 steps), 256 threads = 8 warps (4m x 2n),
// warp tile 64x64. Fragment-permuted smem (word = f16x2 k-pair):
//   A word idx: ((kk*16 + mi)*4 + r)*32 + lane    r = hi + 2*(pair>=4)
//   B word idx: ((kk*16 + ni)*2 + r)*32 + lane    r = (pair>=4)
// One 16B gmem chunk (8 halfs, 4 pairs) = one conflict-free STS.128.
// Consumer: coalesced conflict-free LDS.32.
// Requires M%256==0, Nout%128==0, K%32==0 (exact: 100352, {1152,384}, 384).
// ---------------------------------------------------------------------------
__global__ __launch_bounds__(256, 1) void gemm_f16_v4(
    const __half* __restrict__ A,
    const __half* __restrict__ W,
    const float* __restrict__ bias,
    float* __restrict__ C,
    int Nout, int K)
{
    __shared__ __align__(16) uint32_t As[2][4096];  // 16KB x2 (256 rows x 16 pairs)
    __shared__ __align__(16) uint32_t Bs[2][2048];  //  8KB x2 (128 rows x 16 pairs)

    const int tid  = threadIdx.x;
    const int bm   = blockIdx.y * 256;
    const int bn   = blockIdx.x * 128;
    const int lane = tid & 31;
    const int warp = tid >> 5;
    const int warp_m = warp >> 1;    // 0..3  (64-row slab)
    const int warp_n = warp & 1;     // 0..1  (64-col slab)
    const int g = lane >> 2;
    const int t = lane & 3;

    // producer mapping: thread (ldr, c): rows ldr+{0,64,128,192}, chunk c (pairs 4c..4c+3)
    const int ldr = tid >> 2;            // 0..63
    const int c   = tid & 3;             // 0..3
    const int kks = c >> 1;              // k16 step of this chunk
    const int ph  = c & 1;               // pair-half (0: pairs 0-3, 1: pairs 4-7)

    const __half* Ab = A + (size_t)(bm + ldr) * K + c * 8;
    const __half* Wb = W + (size_t)(bn + ldr) * K + c * 8;

    int aoff[4], boff[2];
#pragma unroll
    for (int i = 0; i < 4; ++i) {
        const int row = ldr + i * 64;
        const int mi  = row >> 4;
        const int lr  = row & 15;
        const int g2  = lr & 7;
        const int hi  = lr >> 3;
        aoff[i] = ((kks * 16 + mi) * 4 + (hi + 2 * ph)) * 32 + g2 * 4;
    }
#pragma unroll
    for (int i = 0; i < 2; ++i) {
        const int n  = ldr + i * 64;
        const int ni = n >> 3;
        const int g2 = n & 7;
        boff[i] = ((kks * 16 + ni) * 2 + ph) * 32 + g2 * 4;
    }

    uint4 ar[4], wr[2];

    auto load_g = [&](int k0) {
        ar[0] = *(const uint4*)(Ab + k0);
        ar[1] = *(const uint4*)(Ab + (size_t)64  * K + k0);
        ar[2] = *(const uint4*)(Ab + (size_t)128 * K + k0);
        ar[3] = *(const uint4*)(Ab + (size_t)192 * K + k0);
        wr[0] = *(const uint4*)(Wb + k0);
        wr[1] = *(const uint4*)(Wb + (size_t)64  * K + k0);
    };
    auto stash = [&](int bf) {
#pragma unroll
        for (int i = 0; i < 4; ++i) *(uint4*)&As[bf][aoff[i]] = ar[i];
#pragma unroll
        for (int i = 0; i < 2; ++i) *(uint4*)&Bs[bf][boff[i]] = wr[i];
    };

    // prologue
    load_g(0);
    stash(0);
    __syncthreads();

    float acc[4][8][4] = {};

    const int NS = K / 32;   // 12
    int buf = 0;
    for (int s = 0; s < NS; ++s) {
        if (s + 1 < NS) load_g((s + 1) * 32);

#pragma unroll
        for (int kk = 0; kk < 2; ++kk) {
            uint32_t af[4][4], bfr[8][2];
            const uint32_t* Ap = &As[buf][((kk * 16 + warp_m * 4) * 4) * 32 + lane];
            const uint32_t* Bp = &Bs[buf][((kk * 16 + warp_n * 8) * 2) * 32 + lane];
#pragma unroll
            for (int mi = 0; mi < 4; ++mi)
#pragma unroll
                for (int r = 0; r < 4; ++r)
                    af[mi][r] = Ap[(mi * 4 + r) * 32];
#pragma unroll
            for (int ni = 0; ni < 8; ++ni) {
                bfr[ni][0] = Bp[ni * 64];
                bfr[ni][1] = Bp[ni * 64 + 32];
            }
#pragma unroll
            for (int mi = 0; mi < 4; ++mi)
#pragma unroll
                for (int ni = 0; ni < 8; ++ni)
                    mma_f16(acc[mi][ni],
                            af[mi][0], af[mi][1], af[mi][2], af[mi][3],
                            bfr[ni][0], bfr[ni][1]);
        }

        if (s + 1 < NS) {
            stash(buf ^ 1);
            __syncthreads();
            buf ^= 1;
        }
    }

    // epilogue: frag layout m16n8: c0=(g,2t) c1=(g,2t+1) c2=(g+8,2t) c3=(g+8,2t+1)
#pragma unroll
    for (int mi = 0; mi < 4; ++mi) {
#pragma unroll
        for (int ni = 0; ni < 8; ++ni) {
            const int row = bm + warp_m * 64 + mi * 16 + g;
            const int col = bn + warp_n * 64 + ni * 8 + 2 * t;
            const float b0v = __ldg(bias + col);
            const float b1v = __ldg(bias + col + 1);
            float2 v0 = make_float2(acc[mi][ni][0] + b0v, acc[mi][ni][1] + b1v);
            float2 v1 = make_float2(acc[mi][ni][2] + b0v, acc[mi][ni][3] + b1v);
            *(float2*)(C + (size_t)row * Nout + col)       = v0;
            *(float2*)(C + (size_t)(row + 8) * Nout + col) = v1;
        }
    }
}

// ---------------------------------------------------------------------------
// Attention: one CTA (128 threads) per (window b, head h).
// Reads fp32 g_qkv; writes fp16 g_atth (proj GEMM A input).
// ---------------------------------------------------------------------------
__global__ __launch_bounds__(128) void attn_kernel(const float* __restrict__ mask)
{
    const int b = blockIdx.x;
    const int h = blockIdx.y;
    const int tid = threadIdx.x;

    __shared__ __align__(16) float qs[NTOK][DH];
    __shared__ __align__(16) float ks[NTOK][36];
    __shared__ __align__(16) float vs[NTOK][DH];
    __shared__ float sc[NTOK][53];

    const float scale = 0.17677669529663687f;  // 32^-0.5

    for (int idx = tid; idx < NTOK * DH; idx += 128) {
        const int n = idx >> 5;
        const int d = idx & 31;
        const float* base = g_qkv + (size_t)(b * NTOK + n) * THREEC + h * DH + d;
        qs[n][d] = base[0] * scale;
        ks[n][d] = base[CDIM];
        vs[n][d] = base[2 * CDIM];
    }
    __syncthreads();

    // scores: thread (half, j) owns key column j in registers
    {
        const int half = tid >> 6;
        const int j = tid & 63;
        if (j < NTOK) {
            float4 kv[8];
#pragma unroll
            for (int dd = 0; dd < 8; ++dd) kv[dd] = *(const float4*)&ks[j][dd * 4];
            const float* mcol = mask + (size_t)(b & (NWMASK - 1)) * NTOK * NTOK + j;
            const int i0 = half ? 25 : 0;
            const int i1 = half ? NTOK : 25;
            for (int i = i0; i < i1; ++i) {
                const float4* q4 = (const float4*)qs[i];
                float s = 0.0f;
#pragma unroll
                for (int dd = 0; dd < 8; ++dd) {
                    const float4 q = q4[dd];
                    s += q.x * kv[dd].x + q.y * kv[dd].y + q.z * kv[dd].z + q.w * kv[dd].w;
                }
                sc[i][j] = s + mcol[i * NTOK];
            }
        }
    }
    __syncthreads();

    // row softmax
    if (tid < NTOK) {
        float m = -1e30f;
#pragma unroll 7
        for (int j = 0; j < NTOK; j++) m = fmaxf(m, sc[tid][j]);
        float sum = 0.0f;
#pragma unroll 7
        for (int j = 0; j < NTOK; j++) {
            const float e = __expf(sc[tid][j] - m);
            sc[tid][j] = e;
            sum += e;
        }
        const float inv = 1.0f / sum;
#pragma unroll 7
        for (int j = 0; j < NTOK; j++) sc[tid][j] *= inv;
    }
    __syncthreads();

    // P @ V: lane d, warp handles 4-row blocks; store fp16
    const int d = tid & 31;
    const int w = tid >> 5;
    for (int i0 = w * 4; i0 < NTOK; i0 += 16) {
        const int nrows = (NTOK - i0 < 4) ? (NTOK - i0) : 4;
        float o0 = 0.f, o1 = 0.f, o2 = 0.f, o3 = 0.f;
        for (int j = 0; j < NTOK; ++j) {
            const float vj = vs[j][d];
            o0 += sc[i0][j] * vj;
            if (nrows > 1) o1 += sc[i0 + 1][j] * vj;
            if (nrows > 2) o2 += sc[i0 + 2][j] * vj;
            if (nrows > 3) o3 += sc[i0 + 3][j] * vj;
        }
        __half* op = g_atth + (size_t)(b * NTOK + i0) * CDIM + h * DH + d;
        op[0] = __float2half_rn(o0);
        if (nrows > 1) op[CDIM]     = __float2half_rn(o1);
        if (nrows > 2) op[2 * CDIM] = __float2half_rn(o2);
        if (nrows > 3) op[3 * CDIM] = __float2half_rn(o3);
    }
}

// ---------------------------------------------------------------------------
// launch
// ---------------------------------------------------------------------------
extern "C" void kernel_launch(void* const* d_in, const int* in_sizes, int n_in,
                              void* d_out, int out_size)
{
    const float* x      = (const float*)d_in[0];
    const float* mask   = (const float*)d_in[1];
    const float* qkv_w  = (const float*)d_in[2];
    const float* qkv_b  = (const float*)d_in[3];
    const float* proj_w = (const float*)d_in[4];
    const float* proj_b = (const float*)d_in[5];
    float* out = (float*)d_out;

    float* qkv_ptr;
    __half *xh_ptr, *atth_ptr, *wqh_ptr, *wph_ptr;
    cudaGetSymbolAddress((void**)&qkv_ptr,  g_qkv);
    cudaGetSymbolAddress((void**)&xh_ptr,   g_xh);
    cudaGetSymbolAddress((void**)&atth_ptr, g_atth);
    cudaGetSymbolAddress((void**)&wqh_ptr,  g_wqh);
    cudaGetSymbolAddress((void**)&wph_ptr,  g_wph);

    // 0) fp32 -> fp16 prepass (x, both weight matrices)
    {
        const int nx = (MROWS * CDIM) / 8;
        to_half_kernel<<<(nx + 255) / 256, 256>>>(x, xh_ptr, nx);
        const int nq = (THREEC * CDIM) / 8;
        to_half_kernel<<<(nq + 255) / 256, 256>>>(qkv_w, wqh_ptr, nq);
        const int np = (CDIM * CDIM) / 8;
        to_half_kernel<<<(np + 255) / 256, 256>>>(proj_w, wph_ptr, np);
    }
    // 1) QKV GEMM: [100352,384] @ [384,1152]^T (+b), fp16 in / fp32 out
    {
        dim3 grid(THREEC / 128, MROWS / 256);   // (9, 392)
        gemm_f16_v4<<<grid, 256>>>(xh_ptr, wqh_ptr, qkv_b, qkv_ptr, THREEC, CDIM);
    }
    // 2) windowed attention (fp32 in, fp16 out)
    {
        dim3 grid(BWIN, HHEADS);
        attn_kernel<<<grid, 128>>>(mask);
    }
    // 3) Proj GEMM: [100352,384] @ [384,384]^T (+b), fp16 in / fp32 out
    {
        dim3 grid(CDIM / 128, MROWS / 256);     // (3, 392)
        gemm_f16_v4<<<grid, 256>>>(atth_ptr, wph_ptr, proj_b, out, CDIM, CDIM);
    }
}

// round 7
// speedup vs baseline: 2.3134x; 1.4946x over previous
#include <cuda_runtime.h>
#include <cuda_fp16.h>
#include <cstdint>

// Problem constants (fixed by reference)
#define BWIN   2048
#define NTOK   49
#define CDIM   384
#define HHEADS 12
#define DH     32
#define NWMASK 64
#define THREEC 1152
#define MROWS  (BWIN * NTOK)   // 100352

// Scratch (allocation-free rule: __device__ globals)
__device__ __half g_qkvh[(size_t)MROWS * THREEC];   // qkv, fp16
__device__ __half g_xh  [(size_t)MROWS * CDIM];     // x, fp16
__device__ __half g_atth[(size_t)MROWS * CDIM];     // attention out, fp16
__device__ __half g_wqh [(size_t)THREEC * CDIM];    // qkv_w, fp16
__device__ __half g_wph [(size_t)CDIM * CDIM];      // proj_w, fp16

// ---------------------------------------------------------------------------
// helpers
// ---------------------------------------------------------------------------
__device__ __forceinline__ void mma_f16_k16(float c[4],
                                            uint32_t a0, uint32_t a1, uint32_t a2, uint32_t a3,
                                            uint32_t b0, uint32_t b1) {
    asm volatile(
        "mma.sync.aligned.m16n8k16.row.col.f32.f16.f16.f32 "
        "{%0,%1,%2,%3}, {%4,%5,%6,%7}, {%8,%9}, {%0,%1,%2,%3};"
        : "+f"(c[0]), "+f"(c[1]), "+f"(c[2]), "+f"(c[3])
        : "r"(a0), "r"(a1), "r"(a2), "r"(a3), "r"(b0), "r"(b1));
}

__device__ __forceinline__ void mma_f16_k8(float c[4],
                                           uint32_t a0, uint32_t a1, uint32_t b0) {
    asm volatile(
        "mma.sync.aligned.m16n8k8.row.col.f32.f16.f16.f32 "
        "{%0,%1,%2,%3}, {%4,%5}, {%6}, {%0,%1,%2,%3};"
        : "+f"(c[0]), "+f"(c[1]), "+f"(c[2]), "+f"(c[3])
        : "r"(a0), "r"(a1), "r"(b0));
}

__device__ __forceinline__ void ldsm4(uint32_t& r0, uint32_t& r1,
                                      uint32_t& r2, uint32_t& r3, uint32_t addr) {
    asm volatile("ldmatrix.sync.aligned.m8n8.x4.shared.b16 {%0,%1,%2,%3}, [%4];"
                 : "=r"(r0), "=r"(r1), "=r"(r2), "=r"(r3) : "r"(addr));
}

__device__ __forceinline__ uint32_t smem_u32(const void* p) {
    return (uint32_t)__cvta_generic_to_shared(p);
}

// ---------------------------------------------------------------------------
// prepass: fp32 -> fp16 (rn); 8 floats per thread
// ---------------------------------------------------------------------------
__global__ void to_half_kernel(const float* __restrict__ in,
                               __half* __restrict__ out, int n8)
{
    const int i = blockIdx.x * blockDim.x + threadIdx.x;
    if (i < n8) {
        const float4 v0 = ((const float4*)in)[2 * i];
        const float4 v1 = ((const float4*)in)[2 * i + 1];
        __half2 h[4];
        h[0] = __floats2half2_rn(v0.x, v0.y);
        h[1] = __floats2half2_rn(v0.z, v0.w);
        h[2] = __floats2half2_rn(v1.x, v1.y);
        h[3] = __floats2half2_rn(v1.z, v1.w);
        ((uint4*)out)[i] = *(uint4*)h;
    }
}

// ---------------------------------------------------------------------------
// fp16 tensor-core GEMM (templated output):  C = A @ W^T + bias, fp32 accum
// CTA 256x128, BK=32 halfs, 8 warps, warp tile 64x64, fragment-permuted smem.
// ---------------------------------------------------------------------------
template <typename TO>
__global__ __launch_bounds__(256, 1) void gemm_f16_v4(
    const __half* __restrict__ A,
    const __half* __restrict__ W,
    const float* __restrict__ bias,
    TO* __restrict__ C,
    int Nout, int K)
{
    __shared__ __align__(16) uint32_t As[2][4096];
    __shared__ __align__(16) uint32_t Bs[2][2048];

    const int tid  = threadIdx.x;
    const int bm   = blockIdx.y * 256;
    const int bn   = blockIdx.x * 128;
    const int lane = tid & 31;
    const int warp = tid >> 5;
    const int warp_m = warp >> 1;
    const int warp_n = warp & 1;
    const int g = lane >> 2;
    const int t = lane & 3;

    const int ldr = tid >> 2;
    const int c   = tid & 3;
    const int kks = c >> 1;
    const int ph  = c & 1;

    const __half* Ab = A + (size_t)(bm + ldr) * K + c * 8;
    const __half* Wb = W + (size_t)(bn + ldr) * K + c * 8;

    int aoff[4], boff[2];
#pragma unroll
    for (int i = 0; i < 4; ++i) {
        const int row = ldr + i * 64;
        const int mi  = row >> 4;
        const int lr  = row & 15;
        const int g2  = lr & 7;
        const int hi  = lr >> 3;
        aoff[i] = ((kks * 16 + mi) * 4 + (hi + 2 * ph)) * 32 + g2 * 4;
    }
#pragma unroll
    for (int i = 0; i < 2; ++i) {
        const int n  = ldr + i * 64;
        const int ni = n >> 3;
        const int g2 = n & 7;
        boff[i] = ((kks * 16 + ni) * 2 + ph) * 32 + g2 * 4;
    }

    uint4 ar[4], wr[2];

    auto load_g = [&](int k0) {
        ar[0] = *(const uint4*)(Ab + k0);
        ar[1] = *(const uint4*)(Ab + (size_t)64  * K + k0);
        ar[2] = *(const uint4*)(Ab + (size_t)128 * K + k0);
        ar[3] = *(const uint4*)(Ab + (size_t)192 * K + k0);
        wr[0] = *(const uint4*)(Wb + k0);
        wr[1] = *(const uint4*)(Wb + (size_t)64  * K + k0);
    };
    auto stash = [&](int bf) {
#pragma unroll
        for (int i = 0; i < 4; ++i) *(uint4*)&As[bf][aoff[i]] = ar[i];
#pragma unroll
        for (int i = 0; i < 2; ++i) *(uint4*)&Bs[bf][boff[i]] = wr[i];
    };

    load_g(0);
    stash(0);
    __syncthreads();

    float acc[4][8][4] = {};

    const int NS = K / 32;
    int buf = 0;
    for (int s = 0; s < NS; ++s) {
        if (s + 1 < NS) load_g((s + 1) * 32);

#pragma unroll
        for (int kk = 0; kk < 2; ++kk) {
            uint32_t af[4][4], bfr[8][2];
            const uint32_t* Ap = &As[buf][((kk * 16 + warp_m * 4) * 4) * 32 + lane];
            const uint32_t* Bp = &Bs[buf][((kk * 16 + warp_n * 8) * 2) * 32 + lane];
#pragma unroll
            for (int mi = 0; mi < 4; ++mi)
#pragma unroll
                for (int r = 0; r < 4; ++r)
                    af[mi][r] = Ap[(mi * 4 + r) * 32];
#pragma unroll
            for (int ni = 0; ni < 8; ++ni) {
                bfr[ni][0] = Bp[ni * 64];
                bfr[ni][1] = Bp[ni * 64 + 32];
            }
#pragma unroll
            for (int mi = 0; mi < 4; ++mi)
#pragma unroll
                for (int ni = 0; ni < 8; ++ni)
                    mma_f16_k16(acc[mi][ni],
                                af[mi][0], af[mi][1], af[mi][2], af[mi][3],
                                bfr[ni][0], bfr[ni][1]);
        }

        if (s + 1 < NS) {
            stash(buf ^ 1);
            __syncthreads();
            buf ^= 1;
        }
    }

#pragma unroll
    for (int mi = 0; mi < 4; ++mi) {
#pragma unroll
        for (int ni = 0; ni < 8; ++ni) {
            const int row = bm + warp_m * 64 + mi * 16 + g;
            const int col = bn + warp_n * 64 + ni * 8 + 2 * t;
            const float b0v = __ldg(bias + col);
            const float b1v = __ldg(bias + col + 1);
            const float v00 = acc[mi][ni][0] + b0v, v01 = acc[mi][ni][1] + b1v;
            const float v10 = acc[mi][ni][2] + b0v, v11 = acc[mi][ni][3] + b1v;
            if constexpr (sizeof(TO) == 2) {
                *(__half2*)((__half*)C + (size_t)row * Nout + col) =
                    __floats2half2_rn(v00, v01);
                *(__half2*)((__half*)C + (size_t)(row + 8) * Nout + col) =
                    __floats2half2_rn(v10, v11);
            } else {
                *(float2*)((float*)C + (size_t)row * Nout + col) = make_float2(v00, v01);
                *(float2*)((float*)C + (size_t)(row + 8) * Nout + col) = make_float2(v10, v11);
            }
        }
    }
}

// ---------------------------------------------------------------------------
// Tensor-core attention: one CTA (128 threads, 4 warps) per (window b, head h).
// Warp w owns m16 tile rows [16w, 16w+16). All fragments in registers.
//  S = Q K^T via m16n8k16 (ldmatrix A/B), mask+scale on C-frags,
//  softmax in regs (quad shfl), P repacked in-register as k8 A-frags,
//  O = P V via m16n8k8 with V transposed in smem.
// ---------------------------------------------------------------------------
__global__ __launch_bounds__(128) void attn_mma(const float* __restrict__ mask)
{
    const int b = blockIdx.x;
    const int h = blockIdx.y;
    const int tid  = threadIdx.x;
    const int lane = tid & 31;
    const int w    = tid >> 5;
    const int g = lane >> 2;
    const int t = lane & 3;

    __shared__ __align__(16) __half qh[64][40];   // 80B rows -> conflict-free ldmatrix
    __shared__ __align__(16) __half kh[64][40];
    __shared__ __align__(16) __half vt[32][72];   // V^T, 144B rows -> conflict-free u32 LDS

    // zero-init (padding rows/cols must be 0)
    for (int i = tid; i < 64 * 20; i += 128) {
        ((uint32_t*)qh)[i] = 0;
        ((uint32_t*)kh)[i] = 0;
    }
    for (int i = tid; i < 32 * 36; i += 128) ((uint32_t*)vt)[i] = 0;
    __syncthreads();

    // load q, k, v (u32 = 2 halfs each)
    const __half* base = g_qkvh + (size_t)(b * NTOK) * THREEC + h * DH;
    for (int idx = tid; idx < NTOK * 16; idx += 128) {
        const int n  = idx >> 4;
        const int d2 = idx & 15;
        const uint32_t* p = (const uint32_t*)(base + (size_t)n * THREEC) + d2;
        const uint32_t q = p[0];
        const uint32_t k = p[CDIM / 2];
        const uint32_t v = p[CDIM];
        *(uint32_t*)&qh[n][d2 * 2] = q;
        *(uint32_t*)&kh[n][d2 * 2] = k;
        const __half2 vh = *(const __half2*)&v;
        vt[d2 * 2][n]     = __low2half(vh);
        vt[d2 * 2 + 1][n] = __high2half(vh);
    }
    __syncthreads();

    const int m0 = w * 16;
    const int r   = lane & 7;
    const int mat = lane >> 3;
    const int lrow = r + (mat & 1) * 8;    // row within 16-block
    const int lcol = (mat >> 1) * 8;       // col within 16-block

    // A fragments (Q), 2 k16 steps
    uint32_t a[2][4];
#pragma unroll
    for (int s = 0; s < 2; ++s)
        ldsm4(a[s][0], a[s][1], a[s][2], a[s][3],
              smem_u32(&qh[m0 + lrow][lcol + s * 16]));

    // S = Q K^T : 7 n-tiles (n = 8*nt), C-frags in fp32
    float c[7][4] = {};
#pragma unroll
    for (int s = 0; s < 2; ++s) {
#pragma unroll
        for (int p = 0; p < 4; ++p) {   // n-tile pair p -> nt = 2p, 2p+1
            uint32_t b0, b1, b2, b3;
            ldsm4(b0, b1, b2, b3, smem_u32(&kh[16 * p + lrow][lcol + s * 16]));
            mma_f16_k16(c[2 * p], a[s][0], a[s][1], a[s][2], a[s][3], b0, b2);
            if (2 * p + 1 < 7)
                mma_f16_k16(c[2 * p + 1], a[s][0], a[s][1], a[s][2], a[s][3], b1, b3);
        }
    }

    // scale + mask, invalid cols -> -1e30
    const float scale = 0.17677669529663687f;   // 32^-0.5
    const float* mrow = mask + (size_t)(b & (NWMASK - 1)) * NTOK * NTOK;
    const int i1 = m0 + g;
    const int i2 = m0 + 8 + g;
    const int mi1 = (i1 < NTOK) ? i1 : NTOK - 1;   // clamp for safe (garbage) rows
    const int mi2 = (i2 < NTOK) ? i2 : NTOK - 1;
#pragma unroll
    for (int nt = 0; nt < 7; ++nt) {
        const int j0 = nt * 8 + 2 * t;
        c[nt][0] = (j0     < NTOK) ? c[nt][0] * scale + __ldg(mrow + mi1 * NTOK + j0)     : -1e30f;
        c[nt][1] = (j0 + 1 < NTOK) ? c[nt][1] * scale + __ldg(mrow + mi1 * NTOK + j0 + 1) : -1e30f;
        c[nt][2] = (j0     < NTOK) ? c[nt][2] * scale + __ldg(mrow + mi2 * NTOK + j0)     : -1e30f;
        c[nt][3] = (j0 + 1 < NTOK) ? c[nt][3] * scale + __ldg(mrow + mi2 * NTOK + j0 + 1) : -1e30f;
    }

    // softmax over j (rows i1, i2 separately), quad shfl reductions
    float mx1 = -1e30f, mx2 = -1e30f;
#pragma unroll
    for (int nt = 0; nt < 7; ++nt) {
        mx1 = fmaxf(mx1, fmaxf(c[nt][0], c[nt][1]));
        mx2 = fmaxf(mx2, fmaxf(c[nt][2], c[nt][3]));
    }
    mx1 = fmaxf(mx1, __shfl_xor_sync(0xffffffffu, mx1, 1));
    mx1 = fmaxf(mx1, __shfl_xor_sync(0xffffffffu, mx1, 2));
    mx2 = fmaxf(mx2, __shfl_xor_sync(0xffffffffu, mx2, 1));
    mx2 = fmaxf(mx2, __shfl_xor_sync(0xffffffffu, mx2, 2));

    float s1 = 0.f, s2 = 0.f;
#pragma unroll
    for (int nt = 0; nt < 7; ++nt) {
        c[nt][0] = __expf(c[nt][0] - mx1);
        c[nt][1] = __expf(c[nt][1] - mx1);
        c[nt][2] = __expf(c[nt][2] - mx2);
        c[nt][3] = __expf(c[nt][3] - mx2);
        s1 += c[nt][0] + c[nt][1];
        s2 += c[nt][2] + c[nt][3];
    }
    s1 += __shfl_xor_sync(0xffffffffu, s1, 1);
    s1 += __shfl_xor_sync(0xffffffffu, s1, 2);
    s2 += __shfl_xor_sync(0xffffffffu, s2, 1);
    s2 += __shfl_xor_sync(0xffffffffu, s2, 2);
    const float inv1 = 1.0f / s1;
    const float inv2 = 1.0f / s2;

    // repack P as m16n8k8 A-frags (fp16)
    uint32_t pa[7][2];
#pragma unroll
    for (int nt = 0; nt < 7; ++nt) {
        const __half2 p0 = __floats2half2_rn(c[nt][0] * inv1, c[nt][1] * inv1);
        const __half2 p1 = __floats2half2_rn(c[nt][2] * inv2, c[nt][3] * inv2);
        pa[nt][0] = *(const uint32_t*)&p0;
        pa[nt][1] = *(const uint32_t*)&p1;
    }

    // O = P V : 4 d-tiles x 7 k8 chunks
    float o[4][4] = {};
#pragma unroll
    for (int kc = 0; kc < 7; ++kc) {
#pragma unroll
        for (int dt = 0; dt < 4; ++dt) {
            const uint32_t bv = *(const uint32_t*)&vt[dt * 8 + g][kc * 8 + 2 * t];
            mma_f16_k8(o[dt], pa[kc][0], pa[kc][1], bv);
        }
    }

    // store O (fp16) into g_atth [B*N, C] at head offset
    __half* ob = g_atth + (size_t)(b * NTOK) * CDIM + h * DH;
#pragma unroll
    for (int dt = 0; dt < 4; ++dt) {
        const int d0 = dt * 8 + 2 * t;
        if (i1 < NTOK)
            *(__half2*)(ob + (size_t)i1 * CDIM + d0) = __floats2half2_rn(o[dt][0], o[dt][1]);
        if (i2 < NTOK)
            *(__half2*)(ob + (size_t)i2 * CDIM + d0) = __floats2half2_rn(o[dt][2], o[dt][3]);
    }
}

// ---------------------------------------------------------------------------
// launch
// ---------------------------------------------------------------------------
extern "C" void kernel_launch(void* const* d_in, const int* in_sizes, int n_in,
                              void* d_out, int out_size)
{
    const float* x      = (const float*)d_in[0];
    const float* mask   = (const float*)d_in[1];
    const float* qkv_w  = (const float*)d_in[2];
    const float* qkv_b  = (const float*)d_in[3];
    const float* proj_w = (const float*)d_in[4];
    const float* proj_b = (const float*)d_in[5];
    float* out = (float*)d_out;

    __half *qkvh_ptr, *xh_ptr, *atth_ptr, *wqh_ptr, *wph_ptr;
    cudaGetSymbolAddress((void**)&qkvh_ptr, g_qkvh);
    cudaGetSymbolAddress((void**)&xh_ptr,   g_xh);
    cudaGetSymbolAddress((void**)&atth_ptr, g_atth);
    cudaGetSymbolAddress((void**)&wqh_ptr,  g_wqh);
    cudaGetSymbolAddress((void**)&wph_ptr,  g_wph);

    // 0) fp32 -> fp16 prepass
    {
        const int nx = (MROWS * CDIM) / 8;
        to_half_kernel<<<(nx + 255) / 256, 256>>>(x, xh_ptr, nx);
        const int nq = (THREEC * CDIM) / 8;
        to_half_kernel<<<(nq + 255) / 256, 256>>>(qkv_w, wqh_ptr, nq);
        const int np = (CDIM * CDIM) / 8;
        to_half_kernel<<<(np + 255) / 256, 256>>>(proj_w, wph_ptr, np);
    }
    // 1) QKV GEMM: fp16 in / fp16 out
    {
        dim3 grid(THREEC / 128, MROWS / 256);
        gemm_f16_v4<__half><<<grid, 256>>>(xh_ptr, wqh_ptr, qkv_b, qkvh_ptr, THREEC, CDIM);
    }
    // 2) windowed attention (tensor cores, fp16 in/out)
    {
        dim3 grid(BWIN, HHEADS);
        attn_mma<<<grid, 128>>>(mask);
    }
    // 3) Proj GEMM: fp16 in / fp32 out
    {
        dim3 grid(CDIM / 128, MROWS / 256);
        gemm_f16_v4<float><<<grid, 256>>>(atth_ptr, wph_ptr, proj_b, out, CDIM, CDIM);
    }
}